// round 16
// baseline (speedup 1.0000x reference)
#include <cuda_runtime.h>
#include <math.h>

#define N 8192
#define D 1024

// Scratch (allocation-free rule: __device__ globals)
__device__ float g_a[N];            // sigmoid(x @ w)
__device__ int4  g_pack[N];         // {idx, bits(m), bits(c), 0} per column
__device__ int   g_rowstart[N + 2]; // lower_bound(idx >= j), j in [0, N+1]

// evict-first 128-bit store: out is write-once/never-read -> don't let it
// displace x in L2. (Legal on sm_103; the ld evict_last variant is not for
// .v4.f32 and is omitted.)
__device__ __forceinline__ void stg_cs_v4(float4* addr, const float4 v) {
    asm volatile("st.global.cs.v4.f32 [%0], {%1,%2,%3,%4};"
                 :: "l"(addr), "f"(v.x), "f"(v.y), "f"(v.z), "f"(v.w)
                 : "memory");
}

// ---------------------------------------------------------------------------
// Kernel 1: z = x @ w, a = sigmoid(z).  One warp per row (R11 exact; best
// measured). Accumulation order bitwise identical -> g_a unchanged.
// ---------------------------------------------------------------------------
__global__ void __launch_bounds__(256) k_logits(const float* __restrict__ x,
                                                const float* __restrict__ w) {
    const int warp = threadIdx.x >> 5;
    const int lane = threadIdx.x & 31;
    const int row  = blockIdx.x * 8 + warp;

    const float4* xr = reinterpret_cast<const float4*>(x) + (size_t)row * (D / 4);
    const float4* w4 = reinterpret_cast<const float4*>(w);

    float4 xv[8];
#pragma unroll
    for (int k = 0; k < 8; k++)
        xv[k] = xr[lane + 32 * k];

    float s = 0.f;
#pragma unroll
    for (int k = 0; k < 8; k++) {
        const float4 wv = __ldg(&w4[lane + 32 * k]);
        s += xv[k].x * wv.x;
        s += xv[k].y * wv.y;
        s += xv[k].z * wv.z;
        s += xv[k].w * wv.w;
    }
#pragma unroll
    for (int off = 16; off; off >>= 1)
        s += __shfl_xor_sync(0xffffffffu, s, off);

    if (lane == 0) {
        float z = s, a;
        if (z >= 0.f) {
            a = 1.f / (1.f + expf(-z));
        } else {
            float e = expf(z);
            a = e / (1.f + e);
        }
        g_a[row] = a;
    }
}

// ---------------------------------------------------------------------------
// Kernel 2: b = cumsum(a) replicating jax.lax.associative_scan's fp32 tree,
// then per-column {idx, m, c} and the exact rowstart table. (R9/R11 exact.)
// ---------------------------------------------------------------------------
__global__ void k_scan() {
    __shared__ float sh[8192];
    const int tid = threadIdx.x;   // 1024 threads

    for (int i = tid; i < 4096; i += 1024)
        sh[i] = g_a[2 * i] + g_a[2 * i + 1];
    __syncthreads();
    for (int l = 2; l <= 7; l++) {                 // n = 2048 .. 64
        const int n    = N >> l;
        const int off  = 8192 - 2 * (8192 >> l);
        const int offp = 8192 - 2 * (8192 >> (l - 1));
        for (int i = tid; i < n; i += 1024)
            sh[off + i] = sh[offp + 2 * i] + sh[offp + 2 * i + 1];
        __syncthreads();
    }

    if (tid < 32) {
        for (int l = 8; l <= 13; l++) {
            const int n    = N >> l;
            const int off  = 8192 - 2 * (8192 >> l);
            const int offp = 8192 - 2 * (8192 >> (l - 1));
            if (tid < n)
                sh[off + tid] = sh[offp + 2 * tid] + sh[offp + 2 * tid + 1];
            __syncwarp();
        }
        for (int l = 12; l >= 8; l--) {
            const int n    = N >> l;
            const int off  = 8192 - 2 * (8192 >> l);
            const int offc = 8192 - 2 * (8192 >> (l + 1));
            float v = 0.f;
            if (tid < n) {
                if (tid & 1)       v = sh[offc + (tid >> 1)];
                else if (tid == 0) v = sh[off];
                else               v = sh[offc + (tid >> 1) - 1] + sh[off + tid];
            }
            __syncwarp();
            if (tid < n) sh[off + tid] = v;
            __syncwarp();
        }
    }
    __syncthreads();

    for (int l = 7; l >= 1; l--) {                 // n = 64 .. 4096, in place
        const int n    = N >> l;
        const int off  = 8192 - 2 * (8192 >> l);
        const int offc = 8192 - 2 * (8192 >> (l + 1));
        for (int i = tid; i < n; i += 1024) {
            float v;
            if (i & 1)       v = sh[offc + (i >> 1)];
            else if (i == 0) v = sh[off];
            else             v = sh[offc + (i >> 1) - 1] + sh[off + i];
            sh[off + i] = v;
        }
        __syncthreads();
    }

    int last_idx = 0;
    for (int i = tid; i < N; i += 1024) {
        const float ai = g_a[i];
        float bi;
        if (i == 0)      bi = ai;
        else if (i & 1)  bi = sh[i >> 1];
        else             bi = sh[(i >> 1) - 1] + ai;

        int prev;
        if (i == 0) {
            prev = 0;
        } else {
            const int k = i - 1;
            float bp;
            if (k == 0)      bp = g_a[0];
            else if (k & 1)  bp = sh[k >> 1];
            else             bp = sh[(k >> 1) - 1] + g_a[k];
            prev = (int)floorf(bp);
        }
        const int idx   = (int)floorf(bi);
        const bool same = (idx == prev);
        const float frac = bi - (float)idx;

        const float m = same ? ai : frac;
        const float c = same ? 0.f : (ai - frac);
        g_pack[i] = make_int4(idx, __float_as_int(m), __float_as_int(c), 0);

        if (i == 0) g_rowstart[0] = 0;
        else if (!same) g_rowstart[idx] = i;
        if (i == N - 1) last_idx = idx;
    }
    __syncthreads();

    __shared__ int s_last;
    if (tid == ((N - 1) & 1023)) s_last = last_idx;
    __syncthreads();
    for (int j = s_last + 1 + tid; j <= N + 1; j += 1024)
        g_rowstart[j] = N;
}

// ---------------------------------------------------------------------------
// Kernel 3: gather (R9/R11 arithmetic, exact). One block per output row;
// span [rowstart[j], rowstart[j+2]); lane-parallel pack prefetch + shfl
// broadcast; |w| <= 1e-12 skip. Output stores are evict-first (st.global.cs)
// so out never displaces x in L2.
// ---------------------------------------------------------------------------
__global__ void __launch_bounds__(256) k_gather(const float* __restrict__ x,
                                                float* __restrict__ out) {
    const int j = blockIdx.x;     // output row
    const int t = threadIdx.x;    // 0..255, float4 lanes
    const int lane = t & 31;

    const int s = __ldg(&g_rowstart[j]);
    const int e = __ldg(&g_rowstart[j + 2]);

    float4 acc = make_float4(0.f, 0.f, 0.f, 0.f);
    for (int base = s; base < e; base += 32) {
        float wl = 0.f;
        const int i = base + lane;
        if (i < e) {
            const int4 p = __ldg(&g_pack[i]);
            if (p.x == j)          wl = __int_as_float(p.y);   // m
            else if (p.x == j + 1) wl = __int_as_float(p.z);   // c
        }
        const int cnt = min(32, e - base);
#pragma unroll 4
        for (int k = 0; k < cnt; k++) {
            const float wk = __shfl_sync(0xffffffffu, wl, k);
            if (fabsf(wk) > 1e-12f) {   // warp-uniform; sub-tolerance skip
                const float4 v =
                    reinterpret_cast<const float4*>(x)[(size_t)(base + k) * (D / 4) + t];
                acc.x += wk * v.x;
                acc.y += wk * v.y;
                acc.z += wk * v.z;
                acc.w += wk * v.w;
            }
        }
    }
    stg_cs_v4(reinterpret_cast<float4*>(out) + (size_t)j * (D / 4) + t, acc);
}

// ---------------------------------------------------------------------------
extern "C" void kernel_launch(void* const* d_in, const int* in_sizes, int n_in,
                              void* d_out, int out_size) {
    const float* x = (const float*)d_in[0];   // [8192, 1024] f32
    const float* w = (const float*)d_in[1];   // [1024, 1]    f32
    float* out = (float*)d_out;               // [8192, 1024] f32

    k_logits<<<N / 8, 256>>>(x, w);
    k_scan<<<1, 1024>>>();
    k_gather<<<N, 256>>>(x, out);
}

// round 17
// speedup vs baseline: 1.0051x; 1.0051x over previous
#include <cuda_runtime.h>
#include <math.h>

#define N 8192
#define D 1024

// Scratch (allocation-free rule: __device__ globals)
__device__ float g_a[N];            // sigmoid(x @ w)
__device__ int4  g_pack[N];         // {idx, bits(m), bits(c), 0} per column
__device__ int   g_rowstart[N + 2]; // lower_bound(idx >= j), j in [0, N+1]

// ---------------------------------------------------------------------------
// Kernel 1: z = x @ w, a = sigmoid(z).  One warp per row (R11 exact; best
// measured). Accumulation order bitwise identical -> g_a unchanged.
// ---------------------------------------------------------------------------
__global__ void __launch_bounds__(256) k_logits(const float* __restrict__ x,
                                                const float* __restrict__ w) {
    const int warp = threadIdx.x >> 5;
    const int lane = threadIdx.x & 31;
    const int row  = blockIdx.x * 8 + warp;

    const float4* xr = reinterpret_cast<const float4*>(x) + (size_t)row * (D / 4);
    const float4* w4 = reinterpret_cast<const float4*>(w);

    float4 xv[8];
#pragma unroll
    for (int k = 0; k < 8; k++)
        xv[k] = xr[lane + 32 * k];

    float s = 0.f;
#pragma unroll
    for (int k = 0; k < 8; k++) {
        const float4 wv = __ldg(&w4[lane + 32 * k]);
        s += xv[k].x * wv.x;
        s += xv[k].y * wv.y;
        s += xv[k].z * wv.z;
        s += xv[k].w * wv.w;
    }
#pragma unroll
    for (int off = 16; off; off >>= 1)
        s += __shfl_xor_sync(0xffffffffu, s, off);

    if (lane == 0) {
        float z = s, a;
        if (z >= 0.f) {
            a = 1.f / (1.f + expf(-z));
        } else {
            float e = expf(z);
            a = e / (1.f + e);
        }
        g_a[row] = a;
    }
}

// ---------------------------------------------------------------------------
// Kernel 2: b = cumsum(a) replicating jax.lax.associative_scan's fp32 tree,
// then per-column {idx, m, c} and the exact rowstart table. (R9/R11 exact.)
// ---------------------------------------------------------------------------
__global__ void k_scan() {
    __shared__ float sh[8192];
    const int tid = threadIdx.x;   // 1024 threads

    for (int i = tid; i < 4096; i += 1024)
        sh[i] = g_a[2 * i] + g_a[2 * i + 1];
    __syncthreads();
    for (int l = 2; l <= 7; l++) {                 // n = 2048 .. 64
        const int n    = N >> l;
        const int off  = 8192 - 2 * (8192 >> l);
        const int offp = 8192 - 2 * (8192 >> (l - 1));
        for (int i = tid; i < n; i += 1024)
            sh[off + i] = sh[offp + 2 * i] + sh[offp + 2 * i + 1];
        __syncthreads();
    }

    if (tid < 32) {
        for (int l = 8; l <= 13; l++) {
            const int n    = N >> l;
            const int off  = 8192 - 2 * (8192 >> l);
            const int offp = 8192 - 2 * (8192 >> (l - 1));
            if (tid < n)
                sh[off + tid] = sh[offp + 2 * tid] + sh[offp + 2 * tid + 1];
            __syncwarp();
        }
        for (int l = 12; l >= 8; l--) {
            const int n    = N >> l;
            const int off  = 8192 - 2 * (8192 >> l);
            const int offc = 8192 - 2 * (8192 >> (l + 1));
            float v = 0.f;
            if (tid < n) {
                if (tid & 1)       v = sh[offc + (tid >> 1)];
                else if (tid == 0) v = sh[off];
                else               v = sh[offc + (tid >> 1) - 1] + sh[off + tid];
            }
            __syncwarp();
            if (tid < n) sh[off + tid] = v;
            __syncwarp();
        }
    }
    __syncthreads();

    for (int l = 7; l >= 1; l--) {                 // n = 64 .. 4096, in place
        const int n    = N >> l;
        const int off  = 8192 - 2 * (8192 >> l);
        const int offc = 8192 - 2 * (8192 >> (l + 1));
        for (int i = tid; i < n; i += 1024) {
            float v;
            if (i & 1)       v = sh[offc + (i >> 1)];
            else if (i == 0) v = sh[off];
            else             v = sh[offc + (i >> 1) - 1] + sh[off + i];
            sh[off + i] = v;
        }
        __syncthreads();
    }

    int last_idx = 0;
    for (int i = tid; i < N; i += 1024) {
        const float ai = g_a[i];
        float bi;
        if (i == 0)      bi = ai;
        else if (i & 1)  bi = sh[i >> 1];
        else             bi = sh[(i >> 1) - 1] + ai;

        int prev;
        if (i == 0) {
            prev = 0;
        } else {
            const int k = i - 1;
            float bp;
            if (k == 0)      bp = g_a[0];
            else if (k & 1)  bp = sh[k >> 1];
            else             bp = sh[(k >> 1) - 1] + g_a[k];
            prev = (int)floorf(bp);
        }
        const int idx   = (int)floorf(bi);
        const bool same = (idx == prev);
        const float frac = bi - (float)idx;

        const float m = same ? ai : frac;
        const float c = same ? 0.f : (ai - frac);
        g_pack[i] = make_int4(idx, __float_as_int(m), __float_as_int(c), 0);

        if (i == 0) g_rowstart[0] = 0;
        else if (!same) g_rowstart[idx] = i;
        if (i == N - 1) last_idx = idx;
    }
    __syncthreads();

    __shared__ int s_last;
    if (tid == ((N - 1) & 1023)) s_last = last_idx;
    __syncthreads();
    for (int j = s_last + 1 + tid; j <= N + 1; j += 1024)
        g_rowstart[j] = N;
}

// ---------------------------------------------------------------------------
// Kernel 3: gather, WARP-PER-ROW. 1024 blocks x 8 warps; warp owns output
// row j = warp*1024 + blockIdx.x (strided: busy rows spread evenly across
// blocks/waves). Per column the warp issues 8 independent LDG.128 per lane
// (8x the in-flight bytes of the block-per-row version) and amortizes the
// rowstart/pack prologue over a full row. Per-output-element accumulation
// stays ascending-column with identical FMA expressions -> output bitwise
// unchanged. |w| <= 1e-12 skip retained (validated).
// ---------------------------------------------------------------------------
__global__ void __launch_bounds__(256) k_gather(const float* __restrict__ x,
                                                float* __restrict__ out) {
    const int wid  = threadIdx.x >> 5;      // 0..7
    const int lane = threadIdx.x & 31;
    const int j    = wid * 1024 + blockIdx.x;   // output row (strided map)

    const int s = __ldg(&g_rowstart[j]);
    const int e = __ldg(&g_rowstart[j + 2]);

    float4 acc[8];
#pragma unroll
    for (int q = 0; q < 8; q++)
        acc[q] = make_float4(0.f, 0.f, 0.f, 0.f);

    const float4* x4 = reinterpret_cast<const float4*>(x);

    for (int base = s; base < e; base += 32) {
        // lane-parallel weight computation for up to 32 span columns
        float wl = 0.f;
        const int i = base + lane;
        if (i < e) {
            const int4 p = __ldg(&g_pack[i]);
            if (p.x == j)          wl = __int_as_float(p.y);   // m
            else if (p.x == j + 1) wl = __int_as_float(p.z);   // c
        }
        const int cnt = min(32, e - base);
        for (int k = 0; k < cnt; k++) {
            const float wk = __shfl_sync(0xffffffffu, wl, k);
            if (fabsf(wk) > 1e-12f) {   // warp-uniform; sub-tolerance skip
                const float4* xr = x4 + (size_t)(base + k) * (D / 4) + lane;
                float4 v[8];
#pragma unroll
                for (int q = 0; q < 8; q++)      // 8 independent LDG.128
                    v[q] = xr[32 * q];
#pragma unroll
                for (int q = 0; q < 8; q++) {
                    acc[q].x += wk * v[q].x;
                    acc[q].y += wk * v[q].y;
                    acc[q].z += wk * v[q].z;
                    acc[q].w += wk * v[q].w;
                }
            }
        }
    }

    float4* o = reinterpret_cast<float4*>(out) + (size_t)j * (D / 4) + lane;
#pragma unroll
    for (int q = 0; q < 8; q++)
        o[32 * q] = acc[q];
}

// ---------------------------------------------------------------------------
extern "C" void kernel_launch(void* const* d_in, const int* in_sizes, int n_in,
                              void* d_out, int out_size) {
    const float* x = (const float*)d_in[0];   // [8192, 1024] f32
    const float* w = (const float*)d_in[1];   // [1024, 1]    f32
    float* out = (float*)d_out;               // [8192, 1024] f32

    k_logits<<<N / 8, 256>>>(x, w);
    k_scan<<<1, 1024>>>();
    k_gather<<<N / 8, 256>>>(x, out);
}